// round 7
// baseline (speedup 1.0000x reference)
#include <cuda_runtime.h>
#include <cuda_bf16.h>
#include <math.h>

#define BINS 30
#define P1T 128
#define MAX_ROWS 8192

// Global scratch: per-(bin,row) BCE sums (bin-major) + global bin counts.
// g_cnt is zero at module load; zero_cnt_kernel re-zeroes it at the END of
// each call so every graph replay starts from zero.
__device__ float        g_S[BINS * MAX_ROWS];
__device__ unsigned int g_cnt[BINS];

__global__ void zero_cnt_kernel() {
    if (threadIdx.x < BINS) g_cnt[threadIdx.x] = 0u;
}

// ---------------------------------------------------------------------------
// Pass 1: one block per row, single read of logits+target. Latency-oriented:
//  - per-thread FLOAT histogram (sum only): 15.4KB -> ~11-12 blocks/SM
//  - counts per-WARP via __match_any leader aggregation (512B smem)
//  - next-iteration prefetch of both global loads (MLP 4/warp)
//  - binning uses the accurate fp32 formula (matches reference bin edges;
//    measured rel_err 6.2e-6). Only the BCE *value* uses __logf.
// ---------------------------------------------------------------------------
__global__ void __launch_bounds__(P1T, 11)
pass1_kernel(const float4* __restrict__ logits,
             const int4*  __restrict__ target,
             int rows, int c4)
{
    __shared__ float        s_sum[BINS * P1T];     // 15360 B, slot=b*128+tid
    __shared__ unsigned int s_cnt[4 * 32];         // [warp][bin], 512 B

    const int tid  = threadIdx.x;
    const int warp = tid >> 5;
    const int lane = tid & 31;

    // Zero own histogram column + own warp's counter word -> no pre-loop sync.
    #pragma unroll
    for (int b = 0; b < BINS; b++)
        s_sum[b * P1T + tid] = 0.0f;
    s_cnt[tid] = 0u;       // thread tid zeroes warp (tid>>5)'s bin (tid&31)

    const int row = blockIdx.x;
    const float4* lrow = logits + (size_t)row * c4;
    const int4*   trow = target + (size_t)row * c4;

    int    i = tid;
    bool   valid = (i < c4);
    float4 x;  int4 t;
    if (valid) { x = lrow[i]; t = trow[i]; }

    while (valid) {
        const int  inext = i + P1T;
        const bool vnext = (inext < c4);
        float4 xn; int4 tn;
        if (vnext) { xn = lrow[inext]; tn = trow[inext]; }   // prefetch

        #pragma unroll
        for (int k = 0; k < 4; k++) {
            float xv = (k == 0) ? x.x : (k == 1) ? x.y : (k == 2) ? x.z : x.w;
            int   ti = (k == 0) ? t.x : (k == 1) ? t.y : (k == 2) ? t.z : t.w;
            float tf = (float)ti;

            // accurate sigmoid -> bin (reference-matching fp32 path)
            float e  = expf(-xv);
            float w1 = 1.0f + e;
            float s  = 1.0f / w1;              // IEEE division
            float g  = fabsf(s - tf);
            int   b  = (int)(g * 29.9999f);
            b = b > (BINS - 1) ? (BINS - 1) : b;

            // bce = max(x,0) - x*t + log1p(e^{-|x|}) == x*(1-t) + log(1+e^{-x})
            float bce = xv * (1.0f - tf) + __logf(w1);

            s_sum[b * P1T + tid] += bce;

            // warp-aggregated count: one RMW per distinct bin per warp-step
            unsigned int m = __match_any_sync(__activemask(), b);
            if (lane == __ffs(m) - 1)
                s_cnt[warp * 32 + b] += (unsigned int)__popc(m);
        }

        x = xn; t = tn; i = inext; valid = vnext;
    }
    __syncthreads();

    // Reduce sum columns: warp w handles bins w, w+4, ...
    for (int b = warp; b < BINS; b += 4) {
        float fs = 0.0f;
        #pragma unroll
        for (int k = 0; k < 4; k++)
            fs += s_sum[b * P1T + k * 32 + lane];
        #pragma unroll
        for (int off = 16; off > 0; off >>= 1)
            fs += __shfl_down_sync(0xffffffff, fs, off);
        if (lane == 0)
            g_S[b * rows + row] = fs;
    }

    // Reduce counts: 4 warp arrays -> global atomics (30 per block)
    if (tid < BINS) {
        unsigned int c = s_cnt[tid] + s_cnt[32 + tid] +
                         s_cnt[64 + tid] + s_cnt[96 + tid];
        if (c) atomicAdd(&g_cnt[tid], c);
    }
}

// ---------------------------------------------------------------------------
// Finalize: beta from counts; out[row] = (1/cols) * dot(beta, S[:,row]).
// ---------------------------------------------------------------------------
__global__ void __launch_bounds__(256)
finalize_kernel(float* __restrict__ out, int rows, float inv_cols, float tot)
{
    __shared__ float beta[BINS];
    if (threadIdx.x < 32) {
        unsigned int c = (threadIdx.x < BINS) ? g_cnt[threadIdx.x] : 0u;
        unsigned int nz = __ballot_sync(0xffffffff, c > 0u);
        float nonempty = (float)__popc(nz);
        if (threadIdx.x < BINS)
            beta[threadIdx.x] = tot / fmaxf((float)c * nonempty, 1e-4f);
    }
    __syncthreads();

    int row = blockIdx.x * blockDim.x + threadIdx.x;
    if (row < rows) {
        float acc = 0.0f;
        #pragma unroll
        for (int b = 0; b < BINS; b++)
            acc += beta[b] * g_S[b * rows + row];
        out[row] = acc * inv_cols;
    }
}

// ---------------------------------------------------------------------------
extern "C" void kernel_launch(void* const* d_in, const int* in_sizes, int n_in,
                              void* d_out, int out_size)
{
    const float* logits = (const float*)d_in[0];
    const int*   target = (const int*)d_in[1];
    float*       out    = (float*)d_out;

    int n    = in_sizes[0];          // 33554432
    int rows = out_size;             // 4096
    int cols = n / rows;             // 8192
    int c4   = cols >> 2;

    // pass1 first: ncu's captured launch index (≡0 mod 3) lands on pass1.
    pass1_kernel<<<rows, P1T>>>(
        (const float4*)logits, (const int4*)target, rows, c4);
    finalize_kernel<<<(rows + 255) / 256, 256>>>(
        out, rows, 1.0f / (float)cols, (float)n);
    zero_cnt_kernel<<<1, 32>>>();
}

// round 11
// speedup vs baseline: 1.3800x; 1.3800x over previous
#include <cuda_runtime.h>
#include <cuda_bf16.h>
#include <math.h>

#define BINS 30
#define P1T 128
#define MAX_ROWS 8192

// Global scratch: per-(bin,row) BCE sums (bin-major) + global bin counts.
// g_cnt is zero at module load; zero_cnt_kernel re-zeroes it at the END of
// each call so every graph replay starts from zero.
__device__ float        g_S[BINS * MAX_ROWS];
__device__ unsigned int g_cnt[BINS];

__global__ void zero_cnt_kernel() {
    if (threadIdx.x < BINS) g_cnt[threadIdx.x] = 0u;
}

// ---------------------------------------------------------------------------
// Streamlined EXACT per-element math (reference-matching bin bits):
//   e  = expf(-x); w1 = 1+e; s = 1/w1 (IEEE)   [identical to fp32 reference]
//   g  = t ? 1-s : s        (1-s exact by Sterbenz == fabs(s-1) bits)
//   b  = min(29, (int)(g*29.9999))
//   bce = (t ? 0 : x) + __logf(w1)             (value-only fast log)
// ---------------------------------------------------------------------------
struct BinVal { int slot; float bce; };

__device__ __forceinline__ BinVal elem_math(float xv, int ti, int tid) {
    float e  = expf(-xv);
    float w1 = 1.0f + e;
    float s  = 1.0f / w1;                 // IEEE division
    float g  = ti ? (1.0f - s) : s;
    int   b  = (int)(g * 29.9999f);
    b = b > (BINS - 1) ? (BINS - 1) : b;
    BinVal r;
    r.slot = b * P1T + tid;
    r.bce  = (ti ? 0.0f : xv) + __logf(w1);
    return r;
}

// ---------------------------------------------------------------------------
// Pass 1: one block per row, single read of logits+target.
// Per-thread fused (sum,count) float2 slots: 64-bit phase-split conflict-free.
// 8-element batches: all transcendental chains first (8-way ILP), then the
// 8 smem RMWs (pipeline through the LSU).
// ---------------------------------------------------------------------------
__global__ void __launch_bounds__(P1T)
pass1_kernel(const float4* __restrict__ logits,
             const int4*  __restrict__ target,
             int rows, int c4)
{
    __shared__ float2 s_h[BINS * P1T];    // 30720 B

    const int tid = threadIdx.x;

    #pragma unroll
    for (int b = 0; b < BINS; b++)
        s_h[b * P1T + tid] = make_float2(0.0f, 0.0f);
    // own column only -> no sync needed before hot loop

    const int row = blockIdx.x;
    const float4* lrow = logits + (size_t)row * c4;
    const int4*   trow = target + (size_t)row * c4;

    // c4 = 2048, P1T = 128 -> exactly 16 float4 steps/thread = 8 dual steps.
    int i = tid;
    for (; i + P1T < c4; i += 2 * P1T) {
        float4 x0 = lrow[i];
        float4 x1 = lrow[i + P1T];
        int4   t0 = trow[i];
        int4   t1 = trow[i + P1T];

        BinVal r[8];
        r[0] = elem_math(x0.x, t0.x, tid);
        r[1] = elem_math(x0.y, t0.y, tid);
        r[2] = elem_math(x0.z, t0.z, tid);
        r[3] = elem_math(x0.w, t0.w, tid);
        r[4] = elem_math(x1.x, t1.x, tid);
        r[5] = elem_math(x1.y, t1.y, tid);
        r[6] = elem_math(x1.z, t1.z, tid);
        r[7] = elem_math(x1.w, t1.w, tid);

        #pragma unroll
        for (int k = 0; k < 8; k++) {
            float2 v = s_h[r[k].slot];
            v.x += r[k].bce;
            v.y += 1.0f;
            s_h[r[k].slot] = v;
        }
    }
    // remainder (not taken for 8192 cols, kept for generality)
    for (; i < c4; i += P1T) {
        float4 x = lrow[i];
        int4   t = trow[i];
        BinVal r[4];
        r[0] = elem_math(x.x, t.x, tid);
        r[1] = elem_math(x.y, t.y, tid);
        r[2] = elem_math(x.z, t.z, tid);
        r[3] = elem_math(x.w, t.w, tid);
        #pragma unroll
        for (int k = 0; k < 4; k++) {
            float2 v = s_h[r[k].slot];
            v.x += r[k].bce;
            v.y += 1.0f;
            s_h[r[k].slot] = v;
        }
    }
    __syncthreads();

    // Cross-thread reduce: warp w handles bins w, w+4, ...
    int warp = tid >> 5, lane = tid & 31;
    for (int b = warp; b < BINS; b += 4) {
        float fs = 0.0f, fc = 0.0f;
        #pragma unroll
        for (int k = 0; k < 4; k++) {
            float2 v = s_h[b * P1T + k * 32 + lane];
            fs += v.x;
            fc += v.y;
        }
        #pragma unroll
        for (int off = 16; off > 0; off >>= 1) {
            fs += __shfl_down_sync(0xffffffff, fs, off);
            fc += __shfl_down_sync(0xffffffff, fc, off);
        }
        if (lane == 0) {
            g_S[b * rows + row] = fs;
            unsigned int c = (unsigned int)fc;
            if (c) atomicAdd(&g_cnt[b], c);
        }
    }
}

// ---------------------------------------------------------------------------
// Finalize: beta from counts; out[row] = (1/cols) * dot(beta, S[:,row]).
// ---------------------------------------------------------------------------
__global__ void __launch_bounds__(256)
finalize_kernel(float* __restrict__ out, int rows, float inv_cols, float tot)
{
    __shared__ float beta[BINS];
    if (threadIdx.x < 32) {
        unsigned int c = (threadIdx.x < BINS) ? g_cnt[threadIdx.x] : 0u;
        unsigned int nz = __ballot_sync(0xffffffff, c > 0u);
        float nonempty = (float)__popc(nz);
        if (threadIdx.x < BINS)
            beta[threadIdx.x] = tot / fmaxf((float)c * nonempty, 1e-4f);
    }
    __syncthreads();

    int row = blockIdx.x * blockDim.x + threadIdx.x;
    if (row < rows) {
        float acc = 0.0f;
        #pragma unroll
        for (int b = 0; b < BINS; b++)
            acc += beta[b] * g_S[b * rows + row];
        out[row] = acc * inv_cols;
    }
}

// ---------------------------------------------------------------------------
extern "C" void kernel_launch(void* const* d_in, const int* in_sizes, int n_in,
                              void* d_out, int out_size)
{
    const float* logits = (const float*)d_in[0];
    const int*   target = (const int*)d_in[1];
    float*       out    = (float*)d_out;

    int n    = in_sizes[0];          // 33554432
    int rows = out_size;             // 4096
    int cols = n / rows;             // 8192
    int c4   = cols >> 2;

    // pass1 first: ncu's captured launch index (≡0 mod 3) lands on pass1.
    pass1_kernel<<<rows, P1T>>>(
        (const float4*)logits, (const int4*)target, rows, c4);
    finalize_kernel<<<(rows + 255) / 256, 256>>>(
        out, rows, 1.0f / (float)cols, (float)n);
    zero_cnt_kernel<<<1, 32>>>();
}

// round 12
// speedup vs baseline: 1.4083x; 1.0206x over previous
#include <cuda_runtime.h>
#include <cuda_bf16.h>
#include <math.h>

#define BINS 30
#define P1T 128
#define MAX_ROWS 8192

// Global scratch: per-(bin,row) BCE sums (bin-major) + global bin counts.
// g_cnt is zero at module load; zero_cnt_kernel re-zeroes it at the END of
// each call so every graph replay starts from zero.
__device__ float        g_S[BINS * MAX_ROWS];
__device__ unsigned int g_cnt[BINS];

__global__ void zero_cnt_kernel() {
    if (threadIdx.x < BINS) g_cnt[threadIdx.x] = 0u;
}

// ---------------------------------------------------------------------------
// Streamlined EXACT per-element math (reference-matching bin bits):
//   e  = expf(-x); w1 = 1+e; s = 1/w1 (IEEE)   [identical to fp32 reference]
//   g  = t ? 1-s : s        (1-s exact by Sterbenz == fabs(s-1) bits)
//   b  = min(29, (int)(g*29.9999))
//   bce = (t ? 0 : x) + __logf(w1)             (value-only fast log)
// ---------------------------------------------------------------------------
struct BinVal { int slot; float bce; };

__device__ __forceinline__ BinVal elem_math(float xv, int ti, int tid) {
    float e  = expf(-xv);
    float w1 = 1.0f + e;
    float s  = 1.0f / w1;                 // IEEE division
    float g  = ti ? (1.0f - s) : s;
    int   b  = (int)(g * 29.9999f);
    b = b > (BINS - 1) ? (BINS - 1) : b;
    BinVal r;
    r.slot = b * P1T + tid;
    r.bce  = (ti ? 0.0f : xv) + __logf(w1);
    return r;
}

__device__ __forceinline__ void rmw8(float2* s_h, const BinVal* r) {
    #pragma unroll
    for (int k = 0; k < 8; k++) {
        float2 v = s_h[r[k].slot];
        v.x += r[k].bce;
        v.y += 1.0f;
        s_h[r[k].slot] = v;
    }
}

// ---------------------------------------------------------------------------
// Pass 1: one block per row, single read of logits+target.
// 2-deep software pipeline: batch i+1's four vec4 loads are issued BEFORE
// batch i's math+RMW, keeping 4 global loads in flight per warp (MLP fix for
// the DRAM=30%/issue=45%/occ-insensitive under-MLP signature).
// Per-thread fused (sum,count) float2 slots: 64-bit phase-split conflict-free.
// ---------------------------------------------------------------------------
__global__ void __launch_bounds__(P1T)
pass1_kernel(const float4* __restrict__ logits,
             const int4*  __restrict__ target,
             int rows, int c4)
{
    __shared__ float2 s_h[BINS * P1T];    // 30720 B

    const int tid = threadIdx.x;

    #pragma unroll
    for (int b = 0; b < BINS; b++)
        s_h[b * P1T + tid] = make_float2(0.0f, 0.0f);
    // own column only -> no sync needed before hot loop

    const int row = blockIdx.x;
    const float4* lrow = logits + (size_t)row * c4;
    const int4*   trow = target + (size_t)row * c4;

    // c4 = 2048, P1T = 128 -> exactly 16 float4 steps/thread = 8 dual-batches.
    int i = tid;

    if (i + P1T < c4) {
        // prologue: load batch 0
        float4 x0 = lrow[i];
        float4 x1 = lrow[i + P1T];
        int4   t0 = trow[i];
        int4   t1 = trow[i + P1T];

        for (;;) {
            const int inext = i + 2 * P1T;
            const bool more = (inext + P1T < c4);

            float4 xn0, xn1; int4 tn0, tn1;
            if (more) {                       // prefetch batch i+1 FIRST
                xn0 = lrow[inext];
                xn1 = lrow[inext + P1T];
                tn0 = trow[inext];
                tn1 = trow[inext + P1T];
            }

            BinVal r[8];                      // math on batch i (8-way ILP)
            r[0] = elem_math(x0.x, t0.x, tid);
            r[1] = elem_math(x0.y, t0.y, tid);
            r[2] = elem_math(x0.z, t0.z, tid);
            r[3] = elem_math(x0.w, t0.w, tid);
            r[4] = elem_math(x1.x, t1.x, tid);
            r[5] = elem_math(x1.y, t1.y, tid);
            r[6] = elem_math(x1.z, t1.z, tid);
            r[7] = elem_math(x1.w, t1.w, tid);
            rmw8(s_h, r);

            if (!more) { i = inext; break; }
            x0 = xn0; x1 = xn1; t0 = tn0; t1 = tn1;
            i = inext;
        }
    }
    // remainder (not taken for 8192 cols, kept for generality)
    for (; i < c4; i += P1T) {
        float4 x = lrow[i];
        int4   t = trow[i];
        BinVal r[4];
        r[0] = elem_math(x.x, t.x, tid);
        r[1] = elem_math(x.y, t.y, tid);
        r[2] = elem_math(x.z, t.z, tid);
        r[3] = elem_math(x.w, t.w, tid);
        #pragma unroll
        for (int k = 0; k < 4; k++) {
            float2 v = s_h[r[k].slot];
            v.x += r[k].bce;
            v.y += 1.0f;
            s_h[r[k].slot] = v;
        }
    }
    __syncthreads();

    // Cross-thread reduce: warp w handles bins w, w+4, ...
    int warp = tid >> 5, lane = tid & 31;
    for (int b = warp; b < BINS; b += 4) {
        float fs = 0.0f, fc = 0.0f;
        #pragma unroll
        for (int k = 0; k < 4; k++) {
            float2 v = s_h[b * P1T + k * 32 + lane];
            fs += v.x;
            fc += v.y;
        }
        #pragma unroll
        for (int off = 16; off > 0; off >>= 1) {
            fs += __shfl_down_sync(0xffffffff, fs, off);
            fc += __shfl_down_sync(0xffffffff, fc, off);
        }
        if (lane == 0) {
            g_S[b * rows + row] = fs;
            unsigned int c = (unsigned int)fc;
            if (c) atomicAdd(&g_cnt[b], c);
        }
    }
}

// ---------------------------------------------------------------------------
// Finalize: beta from counts; out[row] = (1/cols) * dot(beta, S[:,row]).
// ---------------------------------------------------------------------------
__global__ void __launch_bounds__(256)
finalize_kernel(float* __restrict__ out, int rows, float inv_cols, float tot)
{
    __shared__ float beta[BINS];
    if (threadIdx.x < 32) {
        unsigned int c = (threadIdx.x < BINS) ? g_cnt[threadIdx.x] : 0u;
        unsigned int nz = __ballot_sync(0xffffffff, c > 0u);
        float nonempty = (float)__popc(nz);
        if (threadIdx.x < BINS)
            beta[threadIdx.x] = tot / fmaxf((float)c * nonempty, 1e-4f);
    }
    __syncthreads();

    int row = blockIdx.x * blockDim.x + threadIdx.x;
    if (row < rows) {
        float acc = 0.0f;
        #pragma unroll
        for (int b = 0; b < BINS; b++)
            acc += beta[b] * g_S[b * rows + row];
        out[row] = acc * inv_cols;
    }
}

// ---------------------------------------------------------------------------
extern "C" void kernel_launch(void* const* d_in, const int* in_sizes, int n_in,
                              void* d_out, int out_size)
{
    const float* logits = (const float*)d_in[0];
    const int*   target = (const int*)d_in[1];
    float*       out    = (float*)d_out;

    int n    = in_sizes[0];          // 33554432
    int rows = out_size;             // 4096
    int cols = n / rows;             // 8192
    int c4   = cols >> 2;

    // pass1 first: ncu's captured launch index (≡0 mod 3) lands on pass1.
    pass1_kernel<<<rows, P1T>>>(
        (const float4*)logits, (const int4*)target, rows, c4);
    finalize_kernel<<<(rows + 255) / 256, 256>>>(
        out, rows, 1.0f / (float)cols, (float)n);
    zero_cnt_kernel<<<1, 32>>>();
}